// round 9
// baseline (speedup 1.0000x reference)
#include <cuda_runtime.h>
#include <cstdint>
#include <cstddef>

#define B_   4
#define T_   2048
#define DM   1024
#define H_   16
#define DH   64
#define NTOK (B_ * T_)   // 8192

// Scratch (allocation-free rule: __device__ globals)
__device__ float g_qkv[(size_t)NTOK * 3 * DM];   // tf32-rounded qkv
__device__ float g_xa [(size_t)NTOK * DM];       // tf32(x), later tf32(attn out)
__device__ float g_wq [(size_t)DM * 3 * DM];     // tf32(w_qkv)
__device__ float g_wo [(size_t)DM * DM];         // tf32(w_out)

__device__ __forceinline__ void cpa16(float* s, const float* g) {
    uint32_t sa = (uint32_t)__cvta_generic_to_shared(s);
    asm volatile("cp.async.cg.shared.global [%0], [%1], 16;\n" :: "r"(sa), "l"(g));
}
__device__ __forceinline__ void cpa_commit() {
    asm volatile("cp.async.commit_group;\n");
}
__device__ __forceinline__ void cpa_wait0() {
    asm volatile("cp.async.wait_group 0;\n");
}
__device__ __forceinline__ void cpa_wait1() {
    asm volatile("cp.async.wait_group 1;\n");
}
__device__ __forceinline__ uint32_t f2tf32(float x) {
    uint32_t r;
    asm("cvt.rna.tf32.f32 %0, %1;" : "=r"(r) : "f"(x));
    return r;
}
__device__ __forceinline__ uint4 cvt4(float4 v) {
    uint4 u;
    u.x = f2tf32(v.x); u.y = f2tf32(v.y);
    u.z = f2tf32(v.z); u.w = f2tf32(v.w);
    return u;
}
__device__ __forceinline__ float ex2(float x) {
    float r;
    asm("ex2.approx.f32 %0, %1;" : "=f"(r) : "f"(x));
    return r;
}
#define MMA_TF32(CC, AF, B0, B1)                                              \
    asm volatile(                                                             \
        "mma.sync.aligned.m16n8k8.row.col.f32.tf32.tf32.f32 "                 \
        "{%0,%1,%2,%3}, {%4,%5,%6,%7}, {%8,%9}, {%0,%1,%2,%3};"               \
        : "+f"((CC)[0]), "+f"((CC)[1]), "+f"((CC)[2]), "+f"((CC)[3])          \
        : "r"((AF)[0]), "r"((AF)[1]), "r"((AF)[2]), "r"((AF)[3]),             \
          "r"(B0), "r"(B1))

// ---------------------------------------------------------------------------
// Pre-pass: round fp32 -> tf32 bit patterns (pure bandwidth).
// ---------------------------------------------------------------------------
__global__ __launch_bounds__(256) void cvt_tf32(const float4* __restrict__ in,
                                                uint4* __restrict__ out)
{
    const size_t i = (size_t)blockIdx.x * 256 + threadIdx.x;
    out[i] = cvt4(in[i]);
}

// ---------------------------------------------------------------------------
// TF32 tensor-core GEMM v2: 256x128 CTA tile, 8 warps (4x2), warp tile 64x64.
// Register-level reuse cuts smem fragment traffic 33% vs the 128x128 version
// (crossbar was 84% of tensor time). k-chunk 32, cp.async double buffer,
// inputs pre-rounded to tf32 => mainloop is pure cp.async + LDS + MMA.
// ---------------------------------------------------------------------------
#define ASTR 36
#define BSTR 136
#define ASZ  (256 * ASTR)
#define BSZ  (32 * BSTR)
#define GEMM_SMEM ((2 * ASZ + 2 * BSZ) * 4)   // 108544 bytes

template<bool CVTOUT>
__global__ __launch_bounds__(256, 1) void tf32_gemm(const float* __restrict__ A,
                                                    const float* __restrict__ Bm,
                                                    float* __restrict__ C,
                                                    int M, int N, int K)
{
    extern __shared__ float sm[];
    float* As = sm;                 // [2][256][ASTR]
    float* Bs = sm + 2 * ASZ;       // [2][32][BSTR]

    const int tid  = threadIdx.x;
    const int lane = tid & 31;
    const int warp = tid >> 5;
    const int wm   = warp >> 1;     // 0..3 (64-row blocks)
    const int wn   = warp & 1;      // 0..1 (64-col blocks)
    const int lr   = lane >> 2;
    const int lc   = lane & 3;
    const int row0 = blockIdx.y << 8;
    const int col0 = blockIdx.x << 7;

    const int ar = tid >> 3;              // 0..31 (A: +it*32, 8 its)
    const int ac = (tid & 7) << 2;
    const int br = tid >> 5;              // 0..7  (B: +it*8, 4 its)
    const int bc = (tid & 31) << 2;

    float acc[4][8][4];
#pragma unroll
    for (int mi = 0; mi < 4; ++mi)
#pragma unroll
        for (int ni = 0; ni < 8; ++ni)
#pragma unroll
            for (int r = 0; r < 4; ++r) acc[mi][ni][r] = 0.f;

    const int nch = K >> 5;
    {
        const float* Ag = A + (size_t)(row0 + ar) * K + ac;
        const float* Bg = Bm + (size_t)br * N + col0 + bc;
#pragma unroll
        for (int it = 0; it < 8; ++it)
            cpa16(As + (ar + it * 32) * ASTR + ac, Ag + (size_t)(it * 32) * K);
#pragma unroll
        for (int it = 0; it < 4; ++it)
            cpa16(Bs + (br + it * 8) * BSTR + bc, Bg + (size_t)(it * 8) * N);
        cpa_commit();
    }

    for (int c = 0; c < nch; ++c) {
        cpa_wait0();
        __syncthreads();

        const int cb = c & 1;
        if (c + 1 < nch) {
            const int nb = (c + 1) & 1;
            const int k0 = (c + 1) << 5;
            const float* Ag = A + (size_t)(row0 + ar) * K + k0 + ac;
            const float* Bg = Bm + (size_t)(k0 + br) * N + col0 + bc;
#pragma unroll
            for (int it = 0; it < 8; ++it)
                cpa16(As + nb * ASZ + (ar + it * 32) * ASTR + ac,
                      Ag + (size_t)(it * 32) * K);
#pragma unroll
            for (int it = 0; it < 4; ++it)
                cpa16(Bs + nb * BSZ + (br + it * 8) * BSTR + bc,
                      Bg + (size_t)(it * 8) * N);
            cpa_commit();
        }

        const uint32_t* as = (const uint32_t*)(As + cb * ASZ);
        const uint32_t* bs = (const uint32_t*)(Bs + cb * BSZ);

#pragma unroll
        for (int kk = 0; kk < 32; kk += 8) {
            uint32_t af[4][4], bf[8][2];
#pragma unroll
            for (int mi = 0; mi < 4; ++mi) {
                const int mrow = (wm << 6) + (mi << 4) + lr;
                const uint32_t* ap = as + mrow * ASTR + kk + lc;
                af[mi][0] = ap[0];
                af[mi][1] = ap[8 * ASTR];
                af[mi][2] = ap[4];
                af[mi][3] = ap[8 * ASTR + 4];
            }
#pragma unroll
            for (int ni = 0; ni < 8; ++ni) {
                const int ncol = (wn << 6) + (ni << 3) + lr;
                const uint32_t* bp = bs + (kk + lc) * BSTR + ncol;
                bf[ni][0] = bp[0];
                bf[ni][1] = bp[4 * BSTR];
            }
#pragma unroll
            for (int mi = 0; mi < 4; ++mi)
#pragma unroll
                for (int ni = 0; ni < 8; ++ni)
                    MMA_TF32(acc[mi][ni], af[mi], bf[ni][0], bf[ni][1]);
        }
    }

#pragma unroll
    for (int mi = 0; mi < 4; ++mi) {
        const int row = row0 + (wm << 6) + (mi << 4) + lr;
#pragma unroll
        for (int ni = 0; ni < 8; ++ni) {
            const int col = col0 + (wn << 6) + (ni << 3) + (lc << 1);
            const float* cc = acc[mi][ni];
            if (CVTOUT) {
                *(uint2*)(C + (size_t)row * N + col) =
                    make_uint2(f2tf32(cc[0]), f2tf32(cc[1]));
                *(uint2*)(C + (size_t)(row + 8) * N + col) =
                    make_uint2(f2tf32(cc[2]), f2tf32(cc[3]));
            } else {
                *(float2*)(C + (size_t)row * N + col) =
                    make_float2(cc[0], cc[1]);
                *(float2*)(C + (size_t)(row + 8) * N + col) =
                    make_float2(cc[2], cc[3]);
            }
        }
    }
}

// ---------------------------------------------------------------------------
// Tensor-core causal flash attention, v4 (unchanged from R8):
// cp.async double-buffered K/V tiles, Q fragments in registers, exp2 softmax.
// CTA = 128 q-rows x one head; 8 warps, 16-row stripes; 64-token K/V tiles.
// ---------------------------------------------------------------------------
#define KSTR 68
#define VSTR 72
#define PSTR 68
#define ATTN_SMEM ((128 * PSTR + 2 * 64 * KSTR + 2 * 64 * VSTR) * 4)  // 106496

__global__ __launch_bounds__(256, 2) void attn_tc(const float* __restrict__ qkv,
                                                  float* __restrict__ out)
{
    extern __shared__ float smm[];
    float* Ps = smm;                        // [128][PSTR]: Q staging, then P
    float* K0 = Ps + 128 * PSTR;
    float* K1 = K0 + 64 * KSTR;
    float* V0 = K1 + 64 * KSTR;
    float* V1 = V0 + 64 * VSTR;

    const int tid  = threadIdx.x;
    const int lane = tid & 31;
    const int warp = tid >> 5;
    const int lr   = lane >> 2;
    const int lc   = lane & 3;
    const int qb   = gridDim.x - 1 - blockIdx.x;   // heavy tiles first
    const int h    = blockIdx.y;
    const int b    = blockIdx.z;
    const int q0   = qb << 7;
    const int wrow = warp << 4;

    const float* bb = qkv + (size_t)b * (T_ * 3 * DM) + h * DH;

    const int fr  = tid >> 4;
    const int fc4 = (tid & 15) << 2;

    {
        const float* kg = bb + DM     + (size_t)fr * (3 * DM) + fc4;
        const float* vg = bb + 2 * DM + (size_t)fr * (3 * DM) + fc4;
#pragma unroll
        for (int it = 0; it < 4; ++it) {
            cpa16(K0 + (fr + it * 16) * KSTR + fc4,
                  kg + (size_t)(it * 16) * (3 * DM));
            cpa16(V0 + (fr + it * 16) * VSTR + fc4,
                  vg + (size_t)(it * 16) * (3 * DM));
        }
        cpa_commit();
    }

    const float QSCALE = 0.1803368867f;     // 0.125 * log2(e)
    for (int i = tid; i < 128 * 16; i += 256) {
        const int r  = i >> 4;
        const int c4 = (i & 15) << 2;
        float4 v = *(const float4*)(bb + (size_t)(q0 + r) * (3 * DM) + c4);
        v.x *= QSCALE; v.y *= QSCALE; v.z *= QSCALE; v.w *= QSCALE;
        *(uint4*)(Ps + r * PSTR + c4) = cvt4(v);
    }
    __syncthreads();

    uint32_t qf[8][4];
#pragma unroll
    for (int kkb = 0; kkb < 8; ++kkb) {
        const uint32_t* qp =
            (const uint32_t*)(Ps + (wrow + lr) * PSTR + kkb * 8 + lc);
        qf[kkb][0] = qp[0];
        qf[kkb][1] = qp[8 * PSTR];
        qf[kkb][2] = qp[4];
        qf[kkb][3] = qp[8 * PSTR + 4];
    }

    float m0 = -1e30f, m1 = -1e30f, l0 = 0.f, l1 = 0.f;
    float oacc[8][4];
#pragma unroll
    for (int ni = 0; ni < 8; ++ni)
#pragma unroll
        for (int r = 0; r < 4; ++r) oacc[ni][r] = 0.f;

    const int gr0 = q0 + wrow + lr;
    const int gr1 = gr0 + 8;
    const int nkt = 2 * qb + 2;

    for (int kt = 0; kt < nkt; ++kt) {
        const int cur = kt & 1;
        if (kt + 1 < nkt) {
            float* Kn = (cur ? K0 : K1);
            float* Vn = (cur ? V0 : V1);
            const int kn0 = (kt + 1) << 6;
            const float* kg = bb + DM     + (size_t)(kn0 + fr) * (3 * DM) + fc4;
            const float* vg = bb + 2 * DM + (size_t)(kn0 + fr) * (3 * DM) + fc4;
#pragma unroll
            for (int it = 0; it < 4; ++it) {
                cpa16(Kn + (fr + it * 16) * KSTR + fc4,
                      kg + (size_t)(it * 16) * (3 * DM));
                cpa16(Vn + (fr + it * 16) * VSTR + fc4,
                      vg + (size_t)(it * 16) * (3 * DM));
            }
            cpa_commit();
            cpa_wait1();
        } else {
            cpa_wait0();
        }
        __syncthreads();

        const float* Ks = cur ? K1 : K0;
        const float* Vs = cur ? V1 : V0;

        float sacc[8][4];
#pragma unroll
        for (int ni = 0; ni < 8; ++ni)
#pragma unroll
            for (int r = 0; r < 4; ++r) sacc[ni][r] = 0.f;

#pragma unroll
        for (int kkb = 0; kkb < 8; ++kkb) {
#pragma unroll
            for (int ni = 0; ni < 8; ++ni) {
                const uint32_t* kp =
                    (const uint32_t*)(Ks + (ni * 8 + lr) * KSTR + kkb * 8 + lc);
                MMA_TF32(sacc[ni], qf[kkb], kp[0], kp[4]);
            }
        }

        if (kt >= 2 * qb) {
            const int k0 = kt << 6;
#pragma unroll
            for (int ni = 0; ni < 8; ++ni) {
                const int cb = k0 + ni * 8 + (lc << 1);
                if (cb     > gr0) sacc[ni][0] = -1e30f;
                if (cb + 1 > gr0) sacc[ni][1] = -1e30f;
                if (cb     > gr1) sacc[ni][2] = -1e30f;
                if (cb + 1 > gr1) sacc[ni][3] = -1e30f;
            }
        }

        float rm0 = -1e30f, rm1 = -1e30f;
#pragma unroll
        for (int ni = 0; ni < 8; ++ni) {
            rm0 = fmaxf(rm0, fmaxf(sacc[ni][0], sacc[ni][1]));
            rm1 = fmaxf(rm1, fmaxf(sacc[ni][2], sacc[ni][3]));
        }
        rm0 = fmaxf(rm0, __shfl_xor_sync(0xffffffffu, rm0, 1, 4));
        rm0 = fmaxf(rm0, __shfl_xor_sync(0xffffffffu, rm0, 2, 4));
        rm1 = fmaxf(rm1, __shfl_xor_sync(0xffffffffu, rm1, 1, 4));
        rm1 = fmaxf(rm1, __shfl_xor_sync(0xffffffffu, rm1, 2, 4));

        const float mn0 = fmaxf(m0, rm0);
        const float mn1 = fmaxf(m1, rm1);
        const float c0f = ex2(m0 - mn0);
        const float c1f = ex2(m1 - mn1);
        m0 = mn0; m1 = mn1;

        float rs0 = 0.f, rs1 = 0.f;
#pragma unroll
        for (int ni = 0; ni < 8; ++ni) {
            sacc[ni][0] = ex2(sacc[ni][0] - mn0);
            sacc[ni][1] = ex2(sacc[ni][1] - mn0);
            sacc[ni][2] = ex2(sacc[ni][2] - mn1);
            sacc[ni][3] = ex2(sacc[ni][3] - mn1);
            rs0 += sacc[ni][0] + sacc[ni][1];
            rs1 += sacc[ni][2] + sacc[ni][3];
        }
        rs0 += __shfl_xor_sync(0xffffffffu, rs0, 1, 4);
        rs0 += __shfl_xor_sync(0xffffffffu, rs0, 2, 4);
        rs1 += __shfl_xor_sync(0xffffffffu, rs1, 1, 4);
        rs1 += __shfl_xor_sync(0xffffffffu, rs1, 2, 4);
        l0 = l0 * c0f + rs0;
        l1 = l1 * c1f + rs1;
#pragma unroll
        for (int ni = 0; ni < 8; ++ni) {
            oacc[ni][0] *= c0f; oacc[ni][1] *= c0f;
            oacc[ni][2] *= c1f; oacc[ni][3] *= c1f;
        }

        {
            float* pr = Ps + (wrow + lr) * PSTR + (lc << 1);
#pragma unroll
            for (int ni = 0; ni < 8; ++ni) {
                *(uint2*)(pr + ni * 8) =
                    make_uint2(f2tf32(sacc[ni][0]), f2tf32(sacc[ni][1]));
                *(uint2*)(pr + 8 * PSTR + ni * 8) =
                    make_uint2(f2tf32(sacc[ni][2]), f2tf32(sacc[ni][3]));
            }
        }
        __syncwarp();

#pragma unroll
        for (int kkb = 0; kkb < 8; ++kkb) {
            uint32_t af[4];
            const uint32_t* pp =
                (const uint32_t*)(Ps + (wrow + lr) * PSTR + kkb * 8 + lc);
            af[0] = pp[0];
            af[1] = pp[8 * PSTR];
            af[2] = pp[4];
            af[3] = pp[8 * PSTR + 4];
#pragma unroll
            for (int ni = 0; ni < 8; ++ni) {
                const uint32_t* vp =
                    (const uint32_t*)(Vs + (kkb * 8 + lc) * VSTR + ni * 8 + lr);
                MMA_TF32(oacc[ni], af, vp[0], vp[4 * VSTR]);
            }
        }
        __syncthreads();
    }

    const float inv0 = 1.f / l0;
    const float inv1 = 1.f / l1;
    float* ob = out + (size_t)(b * T_ + gr0) * DM + h * DH + (lc << 1);
#pragma unroll
    for (int ni = 0; ni < 8; ++ni) {
        *(uint2*)(ob + ni * 8) =
            make_uint2(f2tf32(oacc[ni][0] * inv0), f2tf32(oacc[ni][1] * inv0));
        *(uint2*)(ob + (size_t)8 * DM + ni * 8) =
            make_uint2(f2tf32(oacc[ni][2] * inv1), f2tf32(oacc[ni][3] * inv1));
    }
}

// ---------------------------------------------------------------------------
extern "C" void kernel_launch(void* const* d_in, const int* in_sizes, int n_in,
                              void* d_out, int out_size)
{
    const float* x     = (const float*)d_in[0];
    const float* w_qkv = (const float*)d_in[1];
    const float* w_out = (const float*)d_in[2];
    float* out = (float*)d_out;

    float *qkv, *xa, *wq, *wo;
    cudaGetSymbolAddress((void**)&qkv, g_qkv);
    cudaGetSymbolAddress((void**)&xa,  g_xa);
    cudaGetSymbolAddress((void**)&wq,  g_wq);
    cudaGetSymbolAddress((void**)&wo,  g_wo);

    cudaFuncSetAttribute(tf32_gemm<true>,
                         cudaFuncAttributeMaxDynamicSharedMemorySize, GEMM_SMEM);
    cudaFuncSetAttribute(tf32_gemm<false>,
                         cudaFuncAttributeMaxDynamicSharedMemorySize, GEMM_SMEM);
    cudaFuncSetAttribute(attn_tc,
                         cudaFuncAttributeMaxDynamicSharedMemorySize, ATTN_SMEM);

    // 0) pre-round inputs to tf32 bit patterns
    cvt_tf32<<<(NTOK * DM) / 1024, 256>>>((const float4*)x,       (uint4*)xa);
    cvt_tf32<<<(DM * 3 * DM) / 1024, 256>>>((const float4*)w_qkv, (uint4*)wq);
    cvt_tf32<<<(DM * DM) / 1024, 256>>>((const float4*)w_out,     (uint4*)wo);

    // 1) qkv = x @ w_qkv  (256x128 tiles; epilogue rounds to tf32)
    tf32_gemm<true><<<dim3((3 * DM) / 128, NTOK / 256), 256, GEMM_SMEM>>>(
        xa, wq, qkv, NTOK, 3 * DM, DM);
    // 2) causal flash attention (cp.async pipelined; writes tf32 into xa)
    attn_tc<<<dim3(T_ / 128, H_, B_), 256, ATTN_SMEM>>>(qkv, xa);
    // 3) out = attn @ w_out  (final fp32 output)
    tf32_gemm<false><<<dim3(DM / 128, NTOK / 256), 256, GEMM_SMEM>>>(
        xa, wo, out, NTOK, DM, DM);
}

// round 10
// speedup vs baseline: 1.0411x; 1.0411x over previous
#include <cuda_runtime.h>
#include <cstdint>
#include <cstddef>

#define B_   4
#define T_   2048
#define DM   1024
#define H_   16
#define DH   64
#define NTOK (B_ * T_)   // 8192

// Scratch (allocation-free rule: __device__ globals)
__device__ float g_qkv[(size_t)NTOK * 3 * DM];   // tf32-rounded qkv
__device__ float g_xa [(size_t)NTOK * DM];       // tf32(x), later tf32(attn out)
__device__ float g_wq [(size_t)DM * 3 * DM];     // tf32(w_qkv)
__device__ float g_wo [(size_t)DM * DM];         // tf32(w_out)

__device__ __forceinline__ void cpa16(float* s, const float* g) {
    uint32_t sa = (uint32_t)__cvta_generic_to_shared(s);
    asm volatile("cp.async.cg.shared.global [%0], [%1], 16;\n" :: "r"(sa), "l"(g));
}
__device__ __forceinline__ void cpa_commit() {
    asm volatile("cp.async.commit_group;\n");
}
__device__ __forceinline__ void cpa_wait0() {
    asm volatile("cp.async.wait_group 0;\n");
}
__device__ __forceinline__ uint32_t f2tf32(float x) {
    uint32_t r;
    asm("cvt.rna.tf32.f32 %0, %1;" : "=r"(r) : "f"(x));
    return r;
}
__device__ __forceinline__ uint4 cvt4(float4 v) {
    uint4 u;
    u.x = f2tf32(v.x); u.y = f2tf32(v.y);
    u.z = f2tf32(v.z); u.w = f2tf32(v.w);
    return u;
}
__device__ __forceinline__ float ex2(float x) {
    float r;
    asm("ex2.approx.f32 %0, %1;" : "=f"(r) : "f"(x));
    return r;
}
#define MMA_TF32(CC, AF, B0, B1)                                              \
    asm volatile(                                                             \
        "mma.sync.aligned.m16n8k8.row.col.f32.tf32.tf32.f32 "                 \
        "{%0,%1,%2,%3}, {%4,%5,%6,%7}, {%8,%9}, {%0,%1,%2,%3};"               \
        : "+f"((CC)[0]), "+f"((CC)[1]), "+f"((CC)[2]), "+f"((CC)[3])          \
        : "r"((AF)[0]), "r"((AF)[1]), "r"((AF)[2]), "r"((AF)[3]),             \
          "r"(B0), "r"(B1))

// ---------------------------------------------------------------------------
// Pre-pass: round fp32 -> tf32 bit patterns (pure bandwidth).
// ---------------------------------------------------------------------------
__global__ __launch_bounds__(256) void cvt_tf32(const float4* __restrict__ in,
                                                uint4* __restrict__ out)
{
    const size_t i = (size_t)blockIdx.x * 256 + threadIdx.x;
    out[i] = cvt4(in[i]);
}

// ---------------------------------------------------------------------------
// TF32 tensor-core GEMM (reverted to the known-good R7/R8 config):
// 128x128 CTA tile, k-chunk 32, 256 threads (8 warps, warp tile 32x64),
// cp.async double buffer, inputs pre-rounded => mainloop pure LDS+MMA.
// 96 regs -> 2 CTAs/SM.
// ---------------------------------------------------------------------------
#define ASTR 36
#define BSTR 136
#define ASZ  (128 * ASTR)
#define BSZ  (32 * BSTR)
#define GEMM_SMEM ((2 * ASZ + 2 * BSZ) * 4)   // 71680 bytes

template<bool CVTOUT>
__global__ __launch_bounds__(256) void tf32_gemm(const float* __restrict__ A,
                                                 const float* __restrict__ Bm,
                                                 float* __restrict__ C,
                                                 int M, int N, int K)
{
    extern __shared__ float sm[];
    float* As = sm;
    float* Bs = sm + 2 * ASZ;

    const int tid  = threadIdx.x;
    const int lane = tid & 31;
    const int warp = tid >> 5;
    const int wm   = warp >> 1;
    const int wn   = warp & 1;
    const int lr   = lane >> 2;
    const int lc   = lane & 3;
    const int row0 = blockIdx.y << 7;
    const int col0 = blockIdx.x << 7;

    const int ar = tid >> 3;
    const int ac = (tid & 7) << 2;
    const int br = tid >> 5;
    const int bc = (tid & 31) << 2;

    float acc[2][8][4];
#pragma unroll
    for (int mi = 0; mi < 2; ++mi)
#pragma unroll
        for (int ni = 0; ni < 8; ++ni)
#pragma unroll
            for (int r = 0; r < 4; ++r) acc[mi][ni][r] = 0.f;

    const int nch = K >> 5;
    {
        const float* Ag = A + (size_t)(row0 + ar) * K + ac;
        const float* Bg = Bm + (size_t)br * N + col0 + bc;
#pragma unroll
        for (int it = 0; it < 4; ++it)
            cpa16(As + (ar + it * 32) * ASTR + ac, Ag + (size_t)(it * 32) * K);
#pragma unroll
        for (int it = 0; it < 4; ++it)
            cpa16(Bs + (br + it * 8) * BSTR + bc, Bg + (size_t)(it * 8) * N);
        cpa_commit();
    }

    for (int c = 0; c < nch; ++c) {
        cpa_wait0();
        __syncthreads();

        const int cb = c & 1;
        if (c + 1 < nch) {
            const int nb = (c + 1) & 1;
            const int k0 = (c + 1) << 5;
            const float* Ag = A + (size_t)(row0 + ar) * K + k0 + ac;
            const float* Bg = Bm + (size_t)(k0 + br) * N + col0 + bc;
#pragma unroll
            for (int it = 0; it < 4; ++it)
                cpa16(As + nb * ASZ + (ar + it * 32) * ASTR + ac,
                      Ag + (size_t)(it * 32) * K);
#pragma unroll
            for (int it = 0; it < 4; ++it)
                cpa16(Bs + nb * BSZ + (br + it * 8) * BSTR + bc,
                      Bg + (size_t)(it * 8) * N);
            cpa_commit();
        }

        const uint32_t* as = (const uint32_t*)(As + cb * ASZ);
        const uint32_t* bs = (const uint32_t*)(Bs + cb * BSZ);

#pragma unroll
        for (int kk = 0; kk < 32; kk += 8) {
            uint32_t af[2][4], bf[8][2];
#pragma unroll
            for (int mi = 0; mi < 2; ++mi) {
                const int mrow = (wm << 5) + (mi << 4) + lr;
                const uint32_t* ap = as + mrow * ASTR + kk + lc;
                af[mi][0] = ap[0];
                af[mi][1] = ap[8 * ASTR];
                af[mi][2] = ap[4];
                af[mi][3] = ap[8 * ASTR + 4];
            }
#pragma unroll
            for (int ni = 0; ni < 8; ++ni) {
                const int ncol = (wn << 6) + (ni << 3) + lr;
                const uint32_t* bp = bs + (kk + lc) * BSTR + ncol;
                bf[ni][0] = bp[0];
                bf[ni][1] = bp[4 * BSTR];
            }
#pragma unroll
            for (int mi = 0; mi < 2; ++mi)
#pragma unroll
                for (int ni = 0; ni < 8; ++ni)
                    MMA_TF32(acc[mi][ni], af[mi], bf[ni][0], bf[ni][1]);
        }
    }

#pragma unroll
    for (int mi = 0; mi < 2; ++mi) {
        const int row = row0 + (wm << 5) + (mi << 4) + lr;
#pragma unroll
        for (int ni = 0; ni < 8; ++ni) {
            const int col = col0 + (wn << 6) + (ni << 3) + (lc << 1);
            const float* cc = acc[mi][ni];
            if (CVTOUT) {
                *(uint2*)(C + (size_t)row * N + col) =
                    make_uint2(f2tf32(cc[0]), f2tf32(cc[1]));
                *(uint2*)(C + (size_t)(row + 8) * N + col) =
                    make_uint2(f2tf32(cc[2]), f2tf32(cc[3]));
            } else {
                *(float2*)(C + (size_t)row * N + col) =
                    make_float2(cc[0], cc[1]);
                *(float2*)(C + (size_t)(row + 8) * N + col) =
                    make_float2(cc[2], cc[3]);
            }
        }
    }
}

// ---------------------------------------------------------------------------
// Tensor-core causal flash attention, v5:
// - SINGLE __syncthreads per K-tile: [wait0 -> sync -> prefetch(kt+1) ->
//   compute]. The sync both publishes tile kt and protects buffer !cur
//   (whose last readers finished in iteration kt-1, before this sync).
// - DEFERRED l-reduction: per-lane partial sums carry the same recurrence
//   (corrections are quad-uniform); one quad-reduce in the epilogue. Removes
//   4 of 8 shfls from each tile's serial softmax path.
// - cp.async double-buffered K/V, Q fragments in registers, exp2 softmax.
// CTA = 128 q-rows x one head; 8 warps, 16-row stripes; 64-token K/V tiles.
// ---------------------------------------------------------------------------
#define KSTR 68
#define VSTR 72
#define PSTR 68
#define ATTN_SMEM ((128 * PSTR + 2 * 64 * KSTR + 2 * 64 * VSTR) * 4)  // 106496

__global__ __launch_bounds__(256, 2) void attn_tc(const float* __restrict__ qkv,
                                                  float* __restrict__ out)
{
    extern __shared__ float smm[];
    float* Ps = smm;                        // [128][PSTR]: Q staging, then P
    float* K0 = Ps + 128 * PSTR;
    float* K1 = K0 + 64 * KSTR;
    float* V0 = K1 + 64 * KSTR;
    float* V1 = V0 + 64 * VSTR;

    const int tid  = threadIdx.x;
    const int lane = tid & 31;
    const int warp = tid >> 5;
    const int lr   = lane >> 2;
    const int lc   = lane & 3;
    const int qb   = gridDim.x - 1 - blockIdx.x;   // heavy tiles first
    const int h    = blockIdx.y;
    const int b    = blockIdx.z;
    const int q0   = qb << 7;
    const int wrow = warp << 4;

    const float* bb = qkv + (size_t)b * (T_ * 3 * DM) + h * DH;

    const int fr  = tid >> 4;
    const int fc4 = (tid & 15) << 2;

    // prologue: stream tile 0 while we prep Q
    {
        const float* kg = bb + DM     + (size_t)fr * (3 * DM) + fc4;
        const float* vg = bb + 2 * DM + (size_t)fr * (3 * DM) + fc4;
#pragma unroll
        for (int it = 0; it < 4; ++it) {
            cpa16(K0 + (fr + it * 16) * KSTR + fc4,
                  kg + (size_t)(it * 16) * (3 * DM));
            cpa16(V0 + (fr + it * 16) * VSTR + fc4,
                  vg + (size_t)(it * 16) * (3 * DM));
        }
        cpa_commit();
    }

    const float QSCALE = 0.1803368867f;     // 0.125 * log2(e)
    for (int i = tid; i < 128 * 16; i += 256) {
        const int r  = i >> 4;
        const int c4 = (i & 15) << 2;
        float4 v = *(const float4*)(bb + (size_t)(q0 + r) * (3 * DM) + c4);
        v.x *= QSCALE; v.y *= QSCALE; v.z *= QSCALE; v.w *= QSCALE;
        *(uint4*)(Ps + r * PSTR + c4) = cvt4(v);
    }
    __syncthreads();

    uint32_t qf[8][4];
#pragma unroll
    for (int kkb = 0; kkb < 8; ++kkb) {
        const uint32_t* qp =
            (const uint32_t*)(Ps + (wrow + lr) * PSTR + kkb * 8 + lc);
        qf[kkb][0] = qp[0];
        qf[kkb][1] = qp[8 * PSTR];
        qf[kkb][2] = qp[4];
        qf[kkb][3] = qp[8 * PSTR + 4];
    }

    float m0 = -1e30f, m1 = -1e30f, l0 = 0.f, l1 = 0.f;   // l: per-lane partial
    float oacc[8][4];
#pragma unroll
    for (int ni = 0; ni < 8; ++ni)
#pragma unroll
        for (int r = 0; r < 4; ++r) oacc[ni][r] = 0.f;

    const int gr0 = q0 + wrow + lr;
    const int gr1 = gr0 + 8;
    const int nkt = 2 * qb + 2;

    for (int kt = 0; kt < nkt; ++kt) {
        const int cur = kt & 1;
        cpa_wait0();            // tile kt landed (only group outstanding)
        __syncthreads();        // publish tile kt; all reads of buf !cur done

        if (kt + 1 < nkt) {     // prefetch kt+1 into the other buffer
            float* Kn = (cur ? K0 : K1);
            float* Vn = (cur ? V0 : V1);
            const int kn0 = (kt + 1) << 6;
            const float* kg = bb + DM     + (size_t)(kn0 + fr) * (3 * DM) + fc4;
            const float* vg = bb + 2 * DM + (size_t)(kn0 + fr) * (3 * DM) + fc4;
#pragma unroll
            for (int it = 0; it < 4; ++it) {
                cpa16(Kn + (fr + it * 16) * KSTR + fc4,
                      kg + (size_t)(it * 16) * (3 * DM));
                cpa16(Vn + (fr + it * 16) * VSTR + fc4,
                      vg + (size_t)(it * 16) * (3 * DM));
            }
            cpa_commit();
        }

        const float* Ks = cur ? K1 : K0;
        const float* Vs = cur ? V1 : V0;

        // ---- S = Q @ K^T (16x64 per warp) ----
        float sacc[8][4];
#pragma unroll
        for (int ni = 0; ni < 8; ++ni)
#pragma unroll
            for (int r = 0; r < 4; ++r) sacc[ni][r] = 0.f;

#pragma unroll
        for (int kkb = 0; kkb < 8; ++kkb) {
#pragma unroll
            for (int ni = 0; ni < 8; ++ni) {
                const uint32_t* kp =
                    (const uint32_t*)(Ks + (ni * 8 + lr) * KSTR + kkb * 8 + lc);
                MMA_TF32(sacc[ni], qf[kkb], kp[0], kp[4]);
            }
        }

        // ---- causal mask ----
        if (kt >= 2 * qb) {
            const int k0 = kt << 6;
#pragma unroll
            for (int ni = 0; ni < 8; ++ni) {
                const int cb = k0 + ni * 8 + (lc << 1);
                if (cb     > gr0) sacc[ni][0] = -1e30f;
                if (cb + 1 > gr0) sacc[ni][1] = -1e30f;
                if (cb     > gr1) sacc[ni][2] = -1e30f;
                if (cb + 1 > gr1) sacc[ni][3] = -1e30f;
            }
        }

        // ---- online softmax in exp2 domain (max: quad-reduced; sum: lane-
        //      local partial, reduced once in the epilogue) ----
        float rm0 = -1e30f, rm1 = -1e30f;
#pragma unroll
        for (int ni = 0; ni < 8; ++ni) {
            rm0 = fmaxf(rm0, fmaxf(sacc[ni][0], sacc[ni][1]));
            rm1 = fmaxf(rm1, fmaxf(sacc[ni][2], sacc[ni][3]));
        }
        rm0 = fmaxf(rm0, __shfl_xor_sync(0xffffffffu, rm0, 1, 4));
        rm0 = fmaxf(rm0, __shfl_xor_sync(0xffffffffu, rm0, 2, 4));
        rm1 = fmaxf(rm1, __shfl_xor_sync(0xffffffffu, rm1, 1, 4));
        rm1 = fmaxf(rm1, __shfl_xor_sync(0xffffffffu, rm1, 2, 4));

        const float mn0 = fmaxf(m0, rm0);
        const float mn1 = fmaxf(m1, rm1);
        const float c0f = ex2(m0 - mn0);
        const float c1f = ex2(m1 - mn1);
        m0 = mn0; m1 = mn1;

        float rs0 = 0.f, rs1 = 0.f;
#pragma unroll
        for (int ni = 0; ni < 8; ++ni) {
            sacc[ni][0] = ex2(sacc[ni][0] - mn0);
            sacc[ni][1] = ex2(sacc[ni][1] - mn0);
            sacc[ni][2] = ex2(sacc[ni][2] - mn1);
            sacc[ni][3] = ex2(sacc[ni][3] - mn1);
            rs0 += sacc[ni][0] + sacc[ni][1];
            rs1 += sacc[ni][2] + sacc[ni][3];
        }
        l0 = l0 * c0f + rs0;            // per-lane partial (quad-uniform c0f)
        l1 = l1 * c1f + rs1;
#pragma unroll
        for (int ni = 0; ni < 8; ++ni) {
            oacc[ni][0] *= c0f; oacc[ni][1] *= c0f;
            oacc[ni][2] *= c1f; oacc[ni][3] *= c1f;
        }

        // ---- stage P as tf32 (warp-private rows of Ps) ----
        {
            float* pr = Ps + (wrow + lr) * PSTR + (lc << 1);
#pragma unroll
            for (int ni = 0; ni < 8; ++ni) {
                *(uint2*)(pr + ni * 8) =
                    make_uint2(f2tf32(sacc[ni][0]), f2tf32(sacc[ni][1]));
                *(uint2*)(pr + 8 * PSTR + ni * 8) =
                    make_uint2(f2tf32(sacc[ni][2]), f2tf32(sacc[ni][3]));
            }
        }
        __syncwarp();

        // ---- O += P @ V ----
#pragma unroll
        for (int kkb = 0; kkb < 8; ++kkb) {
            uint32_t af[4];
            const uint32_t* pp =
                (const uint32_t*)(Ps + (wrow + lr) * PSTR + kkb * 8 + lc);
            af[0] = pp[0];
            af[1] = pp[8 * PSTR];
            af[2] = pp[4];
            af[3] = pp[8 * PSTR + 4];
#pragma unroll
            for (int ni = 0; ni < 8; ++ni) {
                const uint32_t* vp =
                    (const uint32_t*)(Vs + (kkb * 8 + lc) * VSTR + ni * 8 + lr);
                MMA_TF32(oacc[ni], af, vp[0], vp[4 * VSTR]);
            }
        }
    }

    // ---- epilogue: final l reduction (deferred), then write tf32 output ----
    l0 += __shfl_xor_sync(0xffffffffu, l0, 1, 4);
    l0 += __shfl_xor_sync(0xffffffffu, l0, 2, 4);
    l1 += __shfl_xor_sync(0xffffffffu, l1, 1, 4);
    l1 += __shfl_xor_sync(0xffffffffu, l1, 2, 4);
    const float inv0 = 1.f / l0;
    const float inv1 = 1.f / l1;
    float* ob = out + (size_t)(b * T_ + gr0) * DM + h * DH + (lc << 1);
#pragma unroll
    for (int ni = 0; ni < 8; ++ni) {
        *(uint2*)(ob + ni * 8) =
            make_uint2(f2tf32(oacc[ni][0] * inv0), f2tf32(oacc[ni][1] * inv0));
        *(uint2*)(ob + (size_t)8 * DM + ni * 8) =
            make_uint2(f2tf32(oacc[ni][2] * inv1), f2tf32(oacc[ni][3] * inv1));
    }
}

// ---------------------------------------------------------------------------
extern "C" void kernel_launch(void* const* d_in, const int* in_sizes, int n_in,
                              void* d_out, int out_size)
{
    const float* x     = (const float*)d_in[0];
    const float* w_qkv = (const float*)d_in[1];
    const float* w_out = (const float*)d_in[2];
    float* out = (float*)d_out;

    float *qkv, *xa, *wq, *wo;
    cudaGetSymbolAddress((void**)&qkv, g_qkv);
    cudaGetSymbolAddress((void**)&xa,  g_xa);
    cudaGetSymbolAddress((void**)&wq,  g_wq);
    cudaGetSymbolAddress((void**)&wo,  g_wo);

    cudaFuncSetAttribute(tf32_gemm<true>,
                         cudaFuncAttributeMaxDynamicSharedMemorySize, GEMM_SMEM);
    cudaFuncSetAttribute(tf32_gemm<false>,
                         cudaFuncAttributeMaxDynamicSharedMemorySize, GEMM_SMEM);
    cudaFuncSetAttribute(attn_tc,
                         cudaFuncAttributeMaxDynamicSharedMemorySize, ATTN_SMEM);

    // 0) pre-round inputs to tf32 bit patterns
    cvt_tf32<<<(NTOK * DM) / 1024, 256>>>((const float4*)x,       (uint4*)xa);
    cvt_tf32<<<(DM * 3 * DM) / 1024, 256>>>((const float4*)w_qkv, (uint4*)wq);
    cvt_tf32<<<(DM * DM) / 1024, 256>>>((const float4*)w_out,     (uint4*)wo);

    // 1) qkv = x @ w_qkv  (128x128 tiles; epilogue rounds to tf32)
    tf32_gemm<true><<<dim3((3 * DM) / 128, NTOK / 128), 256, GEMM_SMEM>>>(
        xa, wq, qkv, NTOK, 3 * DM, DM);
    // 2) causal flash attention (single-sync pipelined; writes tf32 into xa)
    attn_tc<<<dim3(T_ / 128, H_, B_), 256, ATTN_SMEM>>>(qkv, xa);
    // 3) out = attn @ w_out  (final fp32 output)
    tf32_gemm<false><<<dim3(DM / 128, NTOK / 128), 256, GEMM_SMEM>>>(
        xa, wo, out, NTOK, DM, DM);
}